// round 16
// baseline (speedup 1.0000x reference)
#include <cuda_runtime.h>
#include <cuda_bf16.h>
#include <cuda_fp16.h>
#include <stdint.h>

#define NB     16384
#define PD     128
#define PITCH  136                    // bf16 pitch for weight/H tiles (128+8)
#define XPITCH 72                     // fp32 pitch for X staging
#define PITCHF 132
#define XFB64  (64*XPITCH*4)          // 18432 per X buffer (64 rows)
#define WBBYTES (64*PITCH*2)          // 17408 per W1 buffer
#define MLP_SMEM (2*XFB64 + 2*WBBYTES)   // 71680 -> 3 CTAs/SM
#define PB     144                    // byte pitch fp8 B tile in smem
#define LOG_SMEM (128*PB)             // single B tile = 18432

// ---------------- device scratch ----------------
__device__ __nv_bfloat16 g_Wi1[2048*PD];
__device__ __nv_bfloat16 g_Wi2[PD*PD];
__device__ __nv_bfloat16 g_Wn1[256*PD];
__device__ __nv_bfloat16 g_Wn2[PD*PD];
__device__ __nv_bfloat16 g_ip[NB*PD];   // bf16 img embeddings (diag)
__device__ __nv_bfloat16 g_np[NB*PD];   // bf16 num embeddings * log2e/temp (diag)
__device__ uint8_t g_ipp[NB*PD];        // fp8 img embeddings, A-fragment-permuted layout
__device__ uint8_t g_np8[NB*PD];        // fp8 num embeddings, row-major
__device__ float g_rowsum[NB];
__device__ float g_colsum[NB];
__device__ float g_part[64];

// ---------------- asm helpers ----------------
static __device__ __forceinline__ uint32_t smem_u32(const void* p){
    return (uint32_t)__cvta_generic_to_shared(p);
}
static __device__ __forceinline__ void ldsm_x4(uint32_t r[4], uint32_t a){
    asm volatile("ldmatrix.sync.aligned.m8n8.x4.shared.b16 {%0,%1,%2,%3},[%4];"
        : "=r"(r[0]),"=r"(r[1]),"=r"(r[2]),"=r"(r[3]) : "r"(a));
}
static __device__ __forceinline__ void ldsm_x2t(uint32_t r[2], uint32_t a){
    asm volatile("ldmatrix.sync.aligned.m8n8.x2.trans.shared.b16 {%0,%1},[%2];"
        : "=r"(r[0]),"=r"(r[1]) : "r"(a));
}
static __device__ __forceinline__ void mma16816(float c[4], const uint32_t a[4], const uint32_t b[2]){
    asm("mma.sync.aligned.m16n8k16.row.col.f32.bf16.bf16.f32 "
        "{%0,%1,%2,%3},{%4,%5,%6,%7},{%8,%9},{%0,%1,%2,%3};"
        : "+f"(c[0]),"+f"(c[1]),"+f"(c[2]),"+f"(c[3])
        : "r"(a[0]),"r"(a[1]),"r"(a[2]),"r"(a[3]),"r"(b[0]),"r"(b[1]));
}
// fp8 MMA with f16 accumulators (2 regs, f16x2 packed)
static __device__ __forceinline__ void mma_fp8_h(uint32_t c[2], const uint32_t a[4], const uint32_t b[2]){
    asm("mma.sync.aligned.m16n8k32.row.col.f16.e4m3.e4m3.f16 "
        "{%0,%1},{%2,%3,%4,%5},{%6,%7},{%0,%1};"
        : "+r"(c[0]),"+r"(c[1])
        : "r"(a[0]),"r"(a[1]),"r"(a[2]),"r"(a[3]),"r"(b[0]),"r"(b[1]));
}
static __device__ __forceinline__ void mma_fp8_hz(uint32_t d[2], const uint32_t a[4], const uint32_t b[2]){
    asm("mma.sync.aligned.m16n8k32.row.col.f16.e4m3.e4m3.f16 "
        "{%0,%1},{%2,%3,%4,%5},{%6,%7},{%8,%8};"
        : "=r"(d[0]),"=r"(d[1])
        : "r"(a[0]),"r"(a[1]),"r"(a[2]),"r"(a[3]),"r"(b[0]),"r"(b[1]),"r"(0u));
}
static __device__ __forceinline__ uint32_t ex2h2(uint32_t x){
    uint32_t r;
    asm("ex2.approx.f16x2 %0, %1;" : "=r"(r) : "r"(x));
    return r;
}
static __device__ __forceinline__ uint32_t hadd2_(uint32_t a, uint32_t b){
    uint32_t r;
    asm("add.rn.f16x2 %0, %1, %2;" : "=r"(r) : "r"(a), "r"(b));
    return r;
}
static __device__ __forceinline__ uint32_t pack_e4m3(float x0,float x1,float x2,float x3){
    uint32_t r;
    asm("{.reg .b16 lo, hi;\n\t"
        "cvt.rn.satfinite.e4m3x2.f32 lo, %2, %1;\n\t"
        "cvt.rn.satfinite.e4m3x2.f32 hi, %4, %3;\n\t"
        "mov.b32 %0, {lo, hi};}" : "=r"(r) : "f"(x0),"f"(x1),"f"(x2),"f"(x3));
    return r;
}
#define CP16(dst, src) asm volatile("cp.async.cg.shared.global [%0],[%1],16;" \
    :: "r"(dst), "l"(src) : "memory")
#define CP_COMMIT() asm volatile("cp.async.commit_group;" ::: "memory")
#define CP_WAIT0()  asm volatile("cp.async.wait_group 0;" ::: "memory")
#define CP_WAIT1()  asm volatile("cp.async.wait_group 1;" ::: "memory")

// bf16 fragment helpers (pitch PITCH)
static __device__ __forceinline__ void lda(uint32_t a[4], uint32_t base, int m0, int k0, int lane){
    int row = m0 + (lane & 7) + ((lane >> 3) & 1) * 8;
    int kk  = k0 + ((lane >> 4) << 3);
    ldsm_x4(a, base + (uint32_t)(row*PITCH + kk)*2u);
}
static __device__ __forceinline__ void ldb_kn(uint32_t b[2], uint32_t base, int n0, int k0, int lane){
    int row = k0 + (lane & 15);
    ldsm_x2t(b, base + (uint32_t)(row*PITCH + n0)*2u);
}
static __device__ __forceinline__ uint32_t f2frag(const float* XF, int r, int c){
    float2 v = *(const float2*)(XF + r*XPITCH + c);
    __nv_bfloat162 h = __floats2bfloat162_rn(v.x, v.y);
    return *(uint32_t*)&h;
}

// ---------------- fused prep kernel ----------------
__global__ void convert_all(const float* __restrict__ Wi1, const float* __restrict__ Wi2,
                            const float* __restrict__ Wn1, const float* __restrict__ Wn2){
    int i = blockIdx.x*blockDim.x + threadIdx.x;    // 262144 threads
    g_Wi1[i] = __float2bfloat16(Wi1[i]);
    if (i < PD*PD){ g_Wi2[i] = __float2bfloat16(Wi2[i]); g_Wn2[i] = __float2bfloat16(Wn2[i]); }
    if (i < 256*PD) g_Wn1[i] = __float2bfloat16(Wn1[i]);
    if (i < NB){ g_rowsum[i] = 0.f; g_colsum[i] = 0.f; }
}

// ---------------- fused 2-layer MLP + ReLU + L2-norm (64 rows/CTA, 3 CTAs/SM) ----------------
// grid 512: blocks 0..255 img (D=2048), 256..511 num (D=256).
// 256 thr, warp grid 2m x 4n, warp tile 32x32.
__global__ __launch_bounds__(256, 3)
void mlp_all(const float* __restrict__ Ximg, const float* __restrict__ Xnum,
             const float* __restrict__ bi1, const float* __restrict__ bi2,
             const float* __restrict__ bn1, const float* __restrict__ bn2,
             const float* __restrict__ lt)
{
    extern __shared__ char dyn[];
    const int which = blockIdx.x >> 8;
    const int D  = which ? 256 : 2048;
    const int NC = which ? 4 : 32;
    const float* X  = which ? Xnum : Ximg;
    const float* b1g = which ? bn1 : bi1;
    const float* b2g = which ? bn2 : bi2;
    const __nv_bfloat16* W1 = which ? g_Wn1 : g_Wi1;
    const __nv_bfloat16* W2 = which ? g_Wn2 : g_Wi2;
    __nv_bfloat16*       E  = which ? g_np  : g_ip;
    uint8_t*             E8g = which ? g_np8 : (uint8_t*)0;

    const int tid = threadIdx.x, lane = tid & 31, warp = tid >> 5;
    const int wm = warp & 1, wn = warp >> 1;       // 2m x 4n
    const int rowbase = (blockIdx.x & 255) * 64;
    const int fr = lane >> 2, fc = 2*(lane & 3);

    char* XFbuf = dyn;                    // 2 x 18432
    char* WBbuf = dyn + 2*XFB64;          // 2 x 17408

    auto stage = [&](int kc, int b){
        uint32_t xd = smem_u32(XFbuf + b*XFB64);
        #pragma unroll
        for (int it=0; it<4; it++){                  // X chunk: 64 rows x 64 fp32
            int seg = it*256 + tid;
            int r = seg >> 4, s = seg & 15;
            CP16(xd + (uint32_t)(r*(XPITCH*4) + s*16),
                 (const char*)(X + (size_t)(rowbase+r)*D + kc*64) + s*16);
        }
        uint32_t wd = smem_u32(WBbuf + b*WBBYTES);
        #pragma unroll
        for (int it=0; it<4; it++){                  // W1 chunk: 64 rows x 128 bf16
            int seg = it*256 + tid;
            int r = seg >> 4, s = seg & 15;
            CP16(wd + (uint32_t)(r*(PITCH*2) + s*16),
                 (const char*)(W1 + (size_t)(kc*64+r)*PD) + s*16);
        }
    };

    float acc1[2][4][4];
    #pragma unroll
    for (int i=0;i<2;i++)
        #pragma unroll
        for (int j=0;j<4;j++)
            #pragma unroll
            for (int k=0;k<4;k++) acc1[i][j][k] = 0.f;

    stage(0, 0); CP_COMMIT();

    for (int kc = 0; kc < NC; kc++){
        int buf = kc & 1;
        if (kc+1 < NC){ stage(kc+1, buf^1); CP_COMMIT(); CP_WAIT1(); }
        else          { CP_WAIT0(); }
        __syncthreads();
        const float* XF = (const float*)(XFbuf + buf*XFB64);
        const uint32_t wb = smem_u32(WBbuf + buf*WBBYTES);
        #pragma unroll
        for (int ks=0; ks<4; ks++){
            int k0 = ks*16;
            uint32_t a[2][4], b[2];
            #pragma unroll
            for (int mi=0; mi<2; mi++){
                int m0 = wm*32 + mi*16;
                a[mi][0] = f2frag(XF, m0+fr,   k0+fc);
                a[mi][1] = f2frag(XF, m0+fr+8, k0+fc);
                a[mi][2] = f2frag(XF, m0+fr,   k0+fc+8);
                a[mi][3] = f2frag(XF, m0+fr+8, k0+fc+8);
            }
            #pragma unroll
            for (int ni=0; ni<4; ni++){
                ldb_kn(b, wb, wn*32+ni*8, k0, lane);
                mma16816(acc1[0][ni], a[0], b);
                mma16816(acc1[1][ni], a[1], b);
            }
        }
        __syncthreads();
    }

    // bias + relu -> H (64 x PITCH bf16 at dyn[0]); stage W2 (128 x PITCH) at WBbuf
    __nv_bfloat16* H = (__nv_bfloat16*)dyn;
    #pragma unroll
    for (int mi=0; mi<2; mi++)
        #pragma unroll
        for (int ni=0; ni<4; ni++){
            int r0 = wm*32 + mi*16 + fr;
            int c  = wn*32 + ni*8 + fc;
            float ba = b1g[c], bb = b1g[c+1];
            *(__nv_bfloat162*)(H + r0*PITCH + c) =
                __floats2bfloat162_rn(fmaxf(acc1[mi][ni][0]+ba,0.f), fmaxf(acc1[mi][ni][1]+bb,0.f));
            *(__nv_bfloat162*)(H + (r0+8)*PITCH + c) =
                __floats2bfloat162_rn(fmaxf(acc1[mi][ni][2]+ba,0.f), fmaxf(acc1[mi][ni][3]+bb,0.f));
        }
    __nv_bfloat16* W2s = (__nv_bfloat16*)WBbuf;      // 128 x PITCH = 34816 B (both buffers)
    #pragma unroll
    for (int it=0; it<8; it++){
        int idx = it*256 + tid;
        int r = idx >> 4, c8 = (idx & 15)*8;
        *(uint4*)(W2s + r*PITCH + c8) = *(const uint4*)(W2 + (size_t)r*PD + c8);
    }
    __syncthreads();

    float acc2[2][4][4];
    #pragma unroll
    for (int i=0;i<2;i++)
        #pragma unroll
        for (int j=0;j<4;j++)
            #pragma unroll
            for (int k=0;k<4;k++) acc2[i][j][k] = 0.f;

    const uint32_t hb = smem_u32(H), wb2 = smem_u32(W2s);
    #pragma unroll
    for (int ks=0; ks<8; ks++){
        int k0 = ks*16;
        uint32_t a[2][4], b[2];
        lda(a[0], hb, wm*32,    k0, lane);
        lda(a[1], hb, wm*32+16, k0, lane);
        #pragma unroll
        for (int ni=0; ni<4; ni++){
            ldb_kn(b, wb2, wn*32+ni*8, k0, lane);
            mma16816(acc2[0][ni], a[0], b);
            mma16816(acc2[1][ni], a[1], b);
        }
    }
    __syncthreads();

    float* F = (float*)dyn;                          // 64 x PITCHF floats
    #pragma unroll
    for (int mi=0; mi<2; mi++)
        #pragma unroll
        for (int ni=0; ni<4; ni++){
            int r0 = wm*32 + mi*16 + fr;
            int c  = wn*32 + ni*8 + fc;
            F[r0*PITCHF + c]         = acc2[mi][ni][0] + b2g[c];
            F[r0*PITCHF + c + 1]     = acc2[mi][ni][1] + b2g[c+1];
            F[(r0+8)*PITCHF + c]     = acc2[mi][ni][2] + b2g[c];
            F[(r0+8)*PITCHF + c + 1] = acc2[mi][ni][3] + b2g[c+1];
        }
    __syncthreads();

    float scale = which ? 1.44269504088896341f * expf(-lt[0]) : 1.0f;
    #pragma unroll 1
    for (int rr=0; rr<8; rr++){
        int r = warp*8 + rr;
        float4 v = *(const float4*)(F + r*PITCHF + lane*4);
        float s = v.x*v.x + v.y*v.y + v.z*v.z + v.w*v.w;
        #pragma unroll
        for (int o=16; o; o>>=1) s += __shfl_xor_sync(0xffffffffu, s, o);
        float inv = scale / fmaxf(sqrtf(s), 1e-12f);
        float e0 = v.x*inv, e1 = v.y*inv, e2 = v.z*inv, e3 = v.w*inv;
        int gr = rowbase + r;
        __nv_bfloat162* dst = (__nv_bfloat162*)(E + (size_t)gr*PD + lane*4);
        dst[0] = __floats2bfloat162_rn(e0, e1);
        dst[1] = __floats2bfloat162_rn(e2, e3);
        uint32_t w = pack_e4m3(e0, e1, e2, e3);
        if (which){
            *(uint32_t*)(E8g + (size_t)gr*PD + lane*4) = w;          // row-major B
        } else {
            // A-fragment permuted layout (verified R7/R8/R10/R11)
            int ks  = lane >> 3;
            int hi  = (lane >> 2) & 1;
            int fc4 = lane & 3;
            size_t off = (size_t)(gr >> 4)*2048
                       + (size_t)(ks*512 + ((gr & 7)*4 + fc4)*16 + (hi*2 + ((gr >> 3) & 1))*4);
            *(uint32_t*)(g_ipp + off) = w;
        }
    }
}

// ---------------- fp8 logits kernel (R11 verbatim: f16-acc QMMA, 3 CTAs/SM) ----------------
__global__ __launch_bounds__(256, 3)
void logits_fp8()
{
    extern __shared__ uint8_t dyn8[];
    const uint32_t sB = smem_u32(dyn8);
    const int tid = threadIdx.x, lane = tid & 31, warp = tid >> 5;
    const int wm = warp & 3, wn = warp >> 2;
    const int nt = (int)gridDim.x;
    const int t0 = (int)(((long long)blockIdx.x     * 16384) / nt);
    const int t1 = (int)(((long long)(blockIdx.x+1) * 16384) / nt);

    const uint32_t bbase = sB + (uint32_t)((wn*64 + (lane & 7) + ((lane >> 4) << 3))*PB
                                           + (((lane >> 3) & 1) << 4));
    const uint8_t* aBase = g_ipp + (size_t)(wm*2)*2048 + (size_t)lane*16;

    int colb_cur = -1;

    for (int t = t0; t < t1; t++){
        const int colb = t >> 7, rowa = t & 127;
        if (colb != colb_cur){
            __syncthreads();
            const uint8_t* gB = g_np8 + (size_t)colb*128*PD;
            #pragma unroll
            for (int it=0; it<4; it++){
                int seg = it*256 + tid;
                int r = seg >> 3, c = (seg & 7)*16;
                uint4 v = *(const uint4*)(gB + r*PD + c);
                asm volatile("st.shared.v4.b32 [%0],{%1,%2,%3,%4};"
                    :: "r"(sB + (uint32_t)(r*PB + c)), "r"(v.x),"r"(v.y),"r"(v.z),"r"(v.w));
            }
            __syncthreads();
            colb_cur = colb;
        }

        // A fragments: 8 x LDG.128 (coalesced, L2-resident)
        const uint8_t* ap = aBase + (size_t)rowa*16384;
        uint32_t A[8][4];
        #pragma unroll
        for (int mi=0; mi<2; mi++)
            #pragma unroll
            for (int ks=0; ks<4; ks++)
                *(uint4*)A[mi*4+ks] = *(const uint4*)(ap + mi*2048 + ks*512);

        // MMA with f16x2 accumulators
        uint32_t h[2][8][2];
        #pragma unroll
        for (int ks=0; ks<4; ks++)
            #pragma unroll
            for (int np=0; np<4; np++){
                uint32_t b4[4];
                ldsm_x4(b4, bbase + (uint32_t)(np*(16*PB) + ks*32));
                if (ks == 0){
                    mma_fp8_hz(h[0][2*np],   A[0], b4);
                    mma_fp8_hz(h[0][2*np+1], A[0], b4+2);
                    mma_fp8_hz(h[1][2*np],   A[4], b4);
                    mma_fp8_hz(h[1][2*np+1], A[4], b4+2);
                } else {
                    mma_fp8_h(h[0][2*np],   A[ks],   b4);
                    mma_fp8_h(h[0][2*np+1], A[ks],   b4+2);
                    mma_fp8_h(h[1][2*np],   A[4+ks], b4);
                    mma_fp8_h(h[1][2*np+1], A[4+ks], b4+2);
                }
            }

        // exp2 in place (f16x2)
        #pragma unroll
        for (int mi=0; mi<2; mi++)
            #pragma unroll
            for (int ni=0; ni<8; ni++){
                h[mi][ni][0] = ex2h2(h[mi][ni][0]);
                h[mi][ni][1] = ex2h2(h[mi][ni][1]);
            }

        // ---- row sums: HADD2 tree over ni, then lo+hi, shfl over lane&3 ----
        #pragma unroll
        for (int mi=0; mi<2; mi++){
            uint32_t rs0 = h[mi][0][0], rs1 = h[mi][0][1];
            #pragma unroll
            for (int ni=1; ni<8; ni++){
                rs0 = hadd2_(rs0, h[mi][ni][0]);
                rs1 = hadd2_(rs1, h[mi][ni][1]);
            }
            float2 f0 = __half22float2(*(__half2*)&rs0);
            float2 f1 = __half22float2(*(__half2*)&rs1);
            float r0 = f0.x + f0.y;
            float r1 = f1.x + f1.y;
            r0 += __shfl_xor_sync(0xffffffffu, r0, 1);
            r0 += __shfl_xor_sync(0xffffffffu, r0, 2);
            r1 += __shfl_xor_sync(0xffffffffu, r1, 1);
            r1 += __shfl_xor_sync(0xffffffffu, r1, 2);
            if ((lane & 3) == 0){
                int rb = rowa*128 + wm*32 + mi*16 + (lane >> 2);
                atomicAdd(&g_rowsum[rb],     r0);
                atomicAdd(&g_rowsum[rb + 8], r1);
            }
        }

        // ---- col sums: packed HADD2 + 3 shfl per ni ----
        #pragma unroll
        for (int ni=0; ni<8; ni++){
            uint32_t cs = hadd2_(hadd2_(h[0][ni][0], h[0][ni][1]),
                                 hadd2_(h[1][ni][0], h[1][ni][1]));
            cs = hadd2_(cs, __shfl_xor_sync(0xffffffffu, cs, 4));
            cs = hadd2_(cs, __shfl_xor_sync(0xffffffffu, cs, 8));
            cs = hadd2_(cs, __shfl_xor_sync(0xffffffffu, cs, 16));
            if (lane < 4){
                float2 f = __half22float2(*(__half2*)&cs);
                int cb = colb*128 + wn*64 + ni*8 + 2*lane;
                atomicAdd(&g_colsum[cb],     f.x);
                atomicAdd(&g_colsum[cb + 1], f.y);
            }
        }
    }
}

// ---------------- loss assembly ----------------
__global__ void loss_part()
{
    __shared__ float red[256];
    int row = blockIdx.x*256 + threadIdx.x;
    const uint4* pi = (const uint4*)(g_ip + (size_t)row*PD);
    const uint4* pn = (const uint4*)(g_np + (size_t)row*PD);
    float dot = 0.f;
    #pragma unroll
    for (int i=0; i<16; i++){
        uint4 a = pi[i], b = pn[i];
        const __nv_bfloat162* pa = (const __nv_bfloat162*)&a;
        const __nv_bfloat162* pb = (const __nv_bfloat162*)&b;
        #pragma unroll
        for (int j=0; j<4; j++){
            float2 fa = __bfloat1622float2(pa[j]);
            float2 fb = __bfloat1622float2(pb[j]);
            dot += fa.x*fb.x + fa.y*fb.y;
        }
    }
    float val = 0.5f*(logf(g_rowsum[row]) + logf(g_colsum[row]))
              - dot * 0.69314718055994531f;
    red[threadIdx.x] = val;
    __syncthreads();
    #pragma unroll
    for (int o=128; o; o>>=1){
        if (threadIdx.x < o) red[threadIdx.x] += red[threadIdx.x + o];
        __syncthreads();
    }
    if (threadIdx.x == 0) g_part[blockIdx.x] = red[0];
}

__global__ void loss_final(float* out)
{
    int l = threadIdx.x;
    float v = g_part[l] + g_part[l+32];
    #pragma unroll
    for (int o=16; o; o>>=1) v += __shfl_xor_sync(0xffffffffu, v, o);
    if (l == 0) out[0] = v * (1.0f/16384.0f);
}

// ---------------- launcher ----------------
extern "C" void kernel_launch(void* const* d_in, const int* in_sizes, int n_in,
                              void* d_out, int out_size)
{
    (void)in_sizes; (void)n_in; (void)out_size;
    const float* img = (const float*)d_in[0];
    const float* num = (const float*)d_in[1];
    const float* Wi1 = (const float*)d_in[2];
    const float* bi1 = (const float*)d_in[3];
    const float* Wi2 = (const float*)d_in[4];
    const float* bi2 = (const float*)d_in[5];
    const float* Wn1 = (const float*)d_in[6];
    const float* bn1 = (const float*)d_in[7];
    const float* Wn2 = (const float*)d_in[8];
    const float* bn2 = (const float*)d_in[9];
    const float* lt  = (const float*)d_in[10];
    float* out = (float*)d_out;

    int nsm = 148;
    cudaDeviceGetAttribute(&nsm, cudaDevAttrMultiProcessorCount, 0);

    cudaFuncSetAttribute(mlp_all,    cudaFuncAttributeMaxDynamicSharedMemorySize, MLP_SMEM);
    cudaFuncSetAttribute(logits_fp8, cudaFuncAttributeMaxDynamicSharedMemorySize, LOG_SMEM);

    convert_all<<<1024, 256>>>(Wi1, Wi2, Wn1, Wn2);                      // 1
    mlp_all<<<512, 256, MLP_SMEM>>>(img, num, bi1, bi2, bn1, bn2, lt);   // 2
    logits_fp8<<<3*nsm, 256, LOG_SMEM>>>();                              // 3
    loss_part<<<64, 256>>>();                                            // 4
    loss_final<<<1, 32>>>(out);                                          // 5
}

// round 17
// speedup vs baseline: 1.0917x; 1.0917x over previous
#include <cuda_runtime.h>
#include <cuda_bf16.h>
#include <cuda_fp16.h>
#include <stdint.h>

#define NB     16384
#define PD     128
#define PITCH  136                    // bf16 pitch for weight/H tiles (128+8)
#define XPITCH 72                     // fp32 pitch for X staging
#define PITCHF 132
#define XFBYTES (128*XPITCH*4)        // 36864 per buffer
#define WBBYTES (64*PITCH*2)          // 17408 per buffer
#define MLP_SMEM (2*XFBYTES + 2*WBBYTES)   // 108544
#define PB     144                    // byte pitch fp8 B tile in smem
#define LOG_SMEM (128*PB)             // single B tile = 18432

// ---------------- device scratch ----------------
__device__ __nv_bfloat16 g_Wi1[2048*PD];
__device__ __nv_bfloat16 g_Wi2[PD*PD];
__device__ __nv_bfloat16 g_Wn1[256*PD];
__device__ __nv_bfloat16 g_Wn2[PD*PD];
__device__ __nv_bfloat16 g_ip[NB*PD];   // bf16 img embeddings (diag)
__device__ __nv_bfloat16 g_np[NB*PD];   // bf16 num embeddings * log2e/temp (diag)
__device__ uint8_t g_ipp[NB*PD];        // fp8 img embeddings, A-fragment-permuted layout
__device__ uint8_t g_np8[NB*PD];        // fp8 num embeddings, row-major
__device__ float g_rowsum[NB];
__device__ float g_colsum[NB];
__device__ float g_part[128];

// ---------------- asm helpers ----------------
static __device__ __forceinline__ uint32_t smem_u32(const void* p){
    return (uint32_t)__cvta_generic_to_shared(p);
}
static __device__ __forceinline__ void ldsm_x4(uint32_t r[4], uint32_t a){
    asm volatile("ldmatrix.sync.aligned.m8n8.x4.shared.b16 {%0,%1,%2,%3},[%4];"
        : "=r"(r[0]),"=r"(r[1]),"=r"(r[2]),"=r"(r[3]) : "r"(a));
}
static __device__ __forceinline__ void ldsm_x2t(uint32_t r[2], uint32_t a){
    asm volatile("ldmatrix.sync.aligned.m8n8.x2.trans.shared.b16 {%0,%1},[%2];"
        : "=r"(r[0]),"=r"(r[1]) : "r"(a));
}
static __device__ __forceinline__ void mma16816(float c[4], const uint32_t a[4], const uint32_t b[2]){
    asm("mma.sync.aligned.m16n8k16.row.col.f32.bf16.bf16.f32 "
        "{%0,%1,%2,%3},{%4,%5,%6,%7},{%8,%9},{%0,%1,%2,%3};"
        : "+f"(c[0]),"+f"(c[1]),"+f"(c[2]),"+f"(c[3])
        : "r"(a[0]),"r"(a[1]),"r"(a[2]),"r"(a[3]),"r"(b[0]),"r"(b[1]));
}
// fp8 MMA with f16 accumulators (2 regs, f16x2 packed)
static __device__ __forceinline__ void mma_fp8_h(uint32_t c[2], const uint32_t a[4], const uint32_t b[2]){
    asm("mma.sync.aligned.m16n8k32.row.col.f16.e4m3.e4m3.f16 "
        "{%0,%1},{%2,%3,%4,%5},{%6,%7},{%0,%1};"
        : "+r"(c[0]),"+r"(c[1])
        : "r"(a[0]),"r"(a[1]),"r"(a[2]),"r"(a[3]),"r"(b[0]),"r"(b[1]));
}
static __device__ __forceinline__ void mma_fp8_hz(uint32_t d[2], const uint32_t a[4], const uint32_t b[2]){
    asm("mma.sync.aligned.m16n8k32.row.col.f16.e4m3.e4m3.f16 "
        "{%0,%1},{%2,%3,%4,%5},{%6,%7},{%8,%8};"
        : "=r"(d[0]),"=r"(d[1])
        : "r"(a[0]),"r"(a[1]),"r"(a[2]),"r"(a[3]),"r"(b[0]),"r"(b[1]),"r"(0u));
}
static __device__ __forceinline__ uint32_t ex2h2(uint32_t x){
    uint32_t r;
    asm("ex2.approx.f16x2 %0, %1;" : "=r"(r) : "r"(x));
    return r;
}
static __device__ __forceinline__ uint32_t hadd2_(uint32_t a, uint32_t b){
    uint32_t r;
    asm("add.rn.f16x2 %0, %1, %2;" : "=r"(r) : "r"(a), "r"(b));
    return r;
}
static __device__ __forceinline__ uint32_t pack_e4m3(float x0,float x1,float x2,float x3){
    uint32_t r;
    asm("{.reg .b16 lo, hi;\n\t"
        "cvt.rn.satfinite.e4m3x2.f32 lo, %2, %1;\n\t"
        "cvt.rn.satfinite.e4m3x2.f32 hi, %4, %3;\n\t"
        "mov.b32 %0, {lo, hi};}" : "=r"(r) : "f"(x0),"f"(x1),"f"(x2),"f"(x3));
    return r;
}
#define CP16(dst, src) asm volatile("cp.async.cg.shared.global [%0],[%1],16;" \
    :: "r"(dst), "l"(src) : "memory")
#define CP_COMMIT() asm volatile("cp.async.commit_group;" ::: "memory")
#define CP_WAIT0()  asm volatile("cp.async.wait_group 0;" ::: "memory")
#define CP_WAIT1()  asm volatile("cp.async.wait_group 1;" ::: "memory")

// bf16 fragment helpers (pitch PITCH)
static __device__ __forceinline__ void lda(uint32_t a[4], uint32_t base, int m0, int k0, int lane){
    int row = m0 + (lane & 7) + ((lane >> 3) & 1) * 8;
    int kk  = k0 + ((lane >> 4) << 3);
    ldsm_x4(a, base + (uint32_t)(row*PITCH + kk)*2u);
}
static __device__ __forceinline__ void ldb_kn(uint32_t b[2], uint32_t base, int n0, int k0, int lane){
    int row = k0 + (lane & 15);
    ldsm_x2t(b, base + (uint32_t)(row*PITCH + n0)*2u);
}
static __device__ __forceinline__ uint32_t f2frag(const float* XF, int r, int c){
    float2 v = *(const float2*)(XF + r*XPITCH + c);
    __nv_bfloat162 h = __floats2bfloat162_rn(v.x, v.y);
    return *(uint32_t*)&h;
}

// ---------------- fused prep kernel ----------------
__global__ void convert_all(const float* __restrict__ Wi1, const float* __restrict__ Wi2,
                            const float* __restrict__ Wn1, const float* __restrict__ Wn2){
    int i = blockIdx.x*blockDim.x + threadIdx.x;    // 262144 threads
    g_Wi1[i] = __float2bfloat16(Wi1[i]);
    if (i < PD*PD){ g_Wi2[i] = __float2bfloat16(Wi2[i]); g_Wn2[i] = __float2bfloat16(Wn2[i]); }
    if (i < 256*PD) g_Wn1[i] = __float2bfloat16(Wn1[i]);
    if (i < NB){ g_rowsum[i] = 0.f; g_colsum[i] = 0.f; }
}

// ---------------- merged fused MLP + ReLU + L2-norm (R11 version, 128 rows/CTA) ----------------
__global__ __launch_bounds__(256)
void mlp_all(const float* __restrict__ Ximg, const float* __restrict__ Xnum,
             const float* __restrict__ bi1, const float* __restrict__ bi2,
             const float* __restrict__ bn1, const float* __restrict__ bn2,
             const float* __restrict__ lt)
{
    extern __shared__ char dyn[];
    const int which = blockIdx.x >> 7;
    const int D  = which ? 256 : 2048;
    const int NC = which ? 4 : 32;
    const float* X  = which ? Xnum : Ximg;
    const float* b1g = which ? bn1 : bi1;
    const float* b2g = which ? bn2 : bi2;
    const __nv_bfloat16* W1 = which ? g_Wn1 : g_Wi1;
    const __nv_bfloat16* W2 = which ? g_Wn2 : g_Wi2;
    __nv_bfloat16*       E  = which ? g_np  : g_ip;

    const int tid = threadIdx.x, lane = tid & 31, warp = tid >> 5;
    const int wm = warp & 3, wn = warp >> 2;
    const int rowbase = (blockIdx.x & 127) * 128;
    const int fr = lane >> 2, fc = 2*(lane & 3);

    char* XFbuf = dyn;
    char* WBbuf = dyn + 2*XFBYTES;

    auto stage = [&](int kc, int b){
        uint32_t xd = smem_u32(XFbuf + b*XFBYTES);
        #pragma unroll
        for (int it=0; it<8; it++){
            int seg = it*256 + tid;
            int r = seg >> 4, s = seg & 15;
            CP16(xd + (uint32_t)(r*(XPITCH*4) + s*16),
                 (const char*)(X + (size_t)(rowbase+r)*D + kc*64) + s*16);
        }
        uint32_t wd = smem_u32(WBbuf + b*WBBYTES);
        #pragma unroll
        for (int it=0; it<4; it++){
            int seg = it*256 + tid;
            int r = seg >> 4, s = seg & 15;
            CP16(wd + (uint32_t)(r*(PITCH*2) + s*16),
                 (const char*)(W1 + (size_t)(kc*64+r)*PD) + s*16);
        }
    };

    float acc1[2][8][4];
    #pragma unroll
    for (int i=0;i<2;i++)
        #pragma unroll
        for (int j=0;j<8;j++)
            #pragma unroll
            for (int k=0;k<4;k++) acc1[i][j][k] = 0.f;

    stage(0, 0); CP_COMMIT();

    for (int kc = 0; kc < NC; kc++){
        int buf = kc & 1;
        if (kc+1 < NC){ stage(kc+1, buf^1); CP_COMMIT(); CP_WAIT1(); }
        else          { CP_WAIT0(); }
        __syncthreads();
        const float* XF = (const float*)(XFbuf + buf*XFBYTES);
        const uint32_t wb = smem_u32(WBbuf + buf*WBBYTES);
        #pragma unroll
        for (int ks=0; ks<4; ks++){
            int k0 = ks*16;
            uint32_t a[2][4], b[2];
            #pragma unroll
            for (int mi=0; mi<2; mi++){
                int m0 = wm*32 + mi*16;
                a[mi][0] = f2frag(XF, m0+fr,   k0+fc);
                a[mi][1] = f2frag(XF, m0+fr+8, k0+fc);
                a[mi][2] = f2frag(XF, m0+fr,   k0+fc+8);
                a[mi][3] = f2frag(XF, m0+fr+8, k0+fc+8);
            }
            #pragma unroll
            for (int ni=0; ni<8; ni++){
                ldb_kn(b, wb, wn*64+ni*8, k0, lane);
                mma16816(acc1[0][ni], a[0], b);
                mma16816(acc1[1][ni], a[1], b);
            }
        }
        __syncthreads();
    }

    __nv_bfloat16* H = (__nv_bfloat16*)dyn;
    #pragma unroll
    for (int mi=0; mi<2; mi++)
        #pragma unroll
        for (int ni=0; ni<8; ni++){
            int r0 = wm*32 + mi*16 + fr;
            int c  = wn*64 + ni*8 + fc;
            float ba = b1g[c], bb = b1g[c+1];
            *(__nv_bfloat162*)(H + r0*PITCH + c) =
                __floats2bfloat162_rn(fmaxf(acc1[mi][ni][0]+ba,0.f), fmaxf(acc1[mi][ni][1]+bb,0.f));
            *(__nv_bfloat162*)(H + (r0+8)*PITCH + c) =
                __floats2bfloat162_rn(fmaxf(acc1[mi][ni][2]+ba,0.f), fmaxf(acc1[mi][ni][3]+bb,0.f));
        }
    __nv_bfloat16* W2s = (__nv_bfloat16*)WBbuf;
    #pragma unroll
    for (int it=0; it<8; it++){
        int idx = it*256 + tid;
        int r = idx >> 4, c8 = (idx & 15)*8;
        *(uint4*)(W2s + r*PITCH + c8) = *(const uint4*)(W2 + (size_t)r*PD + c8);
    }
    __syncthreads();

    float acc2[2][8][4];
    #pragma unroll
    for (int i=0;i<2;i++)
        #pragma unroll
        for (int j=0;j<8;j++)
            #pragma unroll
            for (int k=0;k<4;k++) acc2[i][j][k] = 0.f;

    const uint32_t hb = smem_u32(H), wb2 = smem_u32(W2s);
    #pragma unroll
    for (int ks=0; ks<8; ks++){
        int k0 = ks*16;
        uint32_t a[2][4], b[2];
        lda(a[0], hb, wm*32,    k0, lane);
        lda(a[1], hb, wm*32+16, k0, lane);
        #pragma unroll
        for (int ni=0; ni<8; ni++){
            ldb_kn(b, wb2, wn*64+ni*8, k0, lane);
            mma16816(acc2[0][ni], a[0], b);
            mma16816(acc2[1][ni], a[1], b);
        }
    }
    __syncthreads();

    float* F = (float*)dyn;
    #pragma unroll
    for (int mi=0; mi<2; mi++)
        #pragma unroll
        for (int ni=0; ni<8; ni++){
            int r0 = wm*32 + mi*16 + fr;
            int c  = wn*64 + ni*8 + fc;
            F[r0*PITCHF + c]         = acc2[mi][ni][0] + b2g[c];
            F[r0*PITCHF + c + 1]     = acc2[mi][ni][1] + b2g[c+1];
            F[(r0+8)*PITCHF + c]     = acc2[mi][ni][2] + b2g[c];
            F[(r0+8)*PITCHF + c + 1] = acc2[mi][ni][3] + b2g[c+1];
        }
    __syncthreads();

    float scale = which ? 1.44269504088896341f * expf(-lt[0]) : 1.0f;
    #pragma unroll 1
    for (int rr=0; rr<16; rr++){
        int r = warp*16 + rr;
        float4 v = *(const float4*)(F + r*PITCHF + lane*4);
        float s = v.x*v.x + v.y*v.y + v.z*v.z + v.w*v.w;
        #pragma unroll
        for (int o=16; o; o>>=1) s += __shfl_xor_sync(0xffffffffu, s, o);
        float inv = scale / fmaxf(sqrtf(s), 1e-12f);
        float e0 = v.x*inv, e1 = v.y*inv, e2 = v.z*inv, e3 = v.w*inv;
        int gr = rowbase + r;
        __nv_bfloat162* dst = (__nv_bfloat162*)(E + (size_t)gr*PD + lane*4);
        dst[0] = __floats2bfloat162_rn(e0, e1);
        dst[1] = __floats2bfloat162_rn(e2, e3);
        uint32_t w = pack_e4m3(e0, e1, e2, e3);
        if (which){
            *(uint32_t*)(g_np8 + (size_t)gr*PD + lane*4) = w;        // row-major B
        } else {
            // A-fragment permuted layout (verified R7/R8/R10/R11)
            int ks  = lane >> 3;
            int hi  = (lane >> 2) & 1;
            int fc4 = lane & 3;
            size_t off = (size_t)(gr >> 4)*2048
                       + (size_t)(ks*512 + ((gr & 7)*4 + fc4)*16 + (hi*2 + ((gr >> 3) & 1))*4);
            *(uint32_t*)(g_ipp + off) = w;
        }
    }
}

// ---------------- fp8 logits kernel (R11 verbatim: f16-acc QMMA, 3 CTAs/SM) ----------------
__global__ __launch_bounds__(256, 3)
void logits_fp8()
{
    extern __shared__ uint8_t dyn8[];
    const uint32_t sB = smem_u32(dyn8);
    const int tid = threadIdx.x, lane = tid & 31, warp = tid >> 5;
    const int wm = warp & 3, wn = warp >> 2;
    const int nt = (int)gridDim.x;
    const int t0 = (int)(((long long)blockIdx.x     * 16384) / nt);
    const int t1 = (int)(((long long)(blockIdx.x+1) * 16384) / nt);

    const uint32_t bbase = sB + (uint32_t)((wn*64 + (lane & 7) + ((lane >> 4) << 3))*PB
                                           + (((lane >> 3) & 1) << 4));
    const uint8_t* aBase = g_ipp + (size_t)(wm*2)*2048 + (size_t)lane*16;

    int colb_cur = -1;

    for (int t = t0; t < t1; t++){
        const int colb = t >> 7, rowa = t & 127;
        if (colb != colb_cur){
            __syncthreads();
            const uint8_t* gB = g_np8 + (size_t)colb*128*PD;
            #pragma unroll
            for (int it=0; it<4; it++){
                int seg = it*256 + tid;
                int r = seg >> 3, c = (seg & 7)*16;
                uint4 v = *(const uint4*)(gB + r*PD + c);
                asm volatile("st.shared.v4.b32 [%0],{%1,%2,%3,%4};"
                    :: "r"(sB + (uint32_t)(r*PB + c)), "r"(v.x),"r"(v.y),"r"(v.z),"r"(v.w));
            }
            __syncthreads();
            colb_cur = colb;
        }

        // A fragments: 8 x LDG.128 (coalesced, L2-resident)
        const uint8_t* ap = aBase + (size_t)rowa*16384;
        uint32_t A[8][4];
        #pragma unroll
        for (int mi=0; mi<2; mi++)
            #pragma unroll
            for (int ks=0; ks<4; ks++)
                *(uint4*)A[mi*4+ks] = *(const uint4*)(ap + mi*2048 + ks*512);

        // MMA with f16x2 accumulators
        uint32_t h[2][8][2];
        #pragma unroll
        for (int ks=0; ks<4; ks++)
            #pragma unroll
            for (int np=0; np<4; np++){
                uint32_t b4[4];
                ldsm_x4(b4, bbase + (uint32_t)(np*(16*PB) + ks*32));
                if (ks == 0){
                    mma_fp8_hz(h[0][2*np],   A[0], b4);
                    mma_fp8_hz(h[0][2*np+1], A[0], b4+2);
                    mma_fp8_hz(h[1][2*np],   A[4], b4);
                    mma_fp8_hz(h[1][2*np+1], A[4], b4+2);
                } else {
                    mma_fp8_h(h[0][2*np],   A[ks],   b4);
                    mma_fp8_h(h[0][2*np+1], A[ks],   b4+2);
                    mma_fp8_h(h[1][2*np],   A[4+ks], b4);
                    mma_fp8_h(h[1][2*np+1], A[4+ks], b4+2);
                }
            }

        // exp2 in place (f16x2)
        #pragma unroll
        for (int mi=0; mi<2; mi++)
            #pragma unroll
            for (int ni=0; ni<8; ni++){
                h[mi][ni][0] = ex2h2(h[mi][ni][0]);
                h[mi][ni][1] = ex2h2(h[mi][ni][1]);
            }

        // ---- row sums: HADD2 tree over ni, then lo+hi, shfl over lane&3 ----
        #pragma unroll
        for (int mi=0; mi<2; mi++){
            uint32_t rs0 = h[mi][0][0], rs1 = h[mi][0][1];
            #pragma unroll
            for (int ni=1; ni<8; ni++){
                rs0 = hadd2_(rs0, h[mi][ni][0]);
                rs1 = hadd2_(rs1, h[mi][ni][1]);
            }
            float2 f0 = __half22float2(*(__half2*)&rs0);
            float2 f1 = __half22float2(*(__half2*)&rs1);
            float r0 = f0.x + f0.y;
            float r1 = f1.x + f1.y;
            r0 += __shfl_xor_sync(0xffffffffu, r0, 1);
            r0 += __shfl_xor_sync(0xffffffffu, r0, 2);
            r1 += __shfl_xor_sync(0xffffffffu, r1, 1);
            r1 += __shfl_xor_sync(0xffffffffu, r1, 2);
            if ((lane & 3) == 0){
                int rb = rowa*128 + wm*32 + mi*16 + (lane >> 2);
                atomicAdd(&g_rowsum[rb],     r0);
                atomicAdd(&g_rowsum[rb + 8], r1);
            }
        }

        // ---- col sums: packed HADD2 + 3 shfl per ni ----
        #pragma unroll
        for (int ni=0; ni<8; ni++){
            uint32_t cs = hadd2_(hadd2_(h[0][ni][0], h[0][ni][1]),
                                 hadd2_(h[1][ni][0], h[1][ni][1]));
            cs = hadd2_(cs, __shfl_xor_sync(0xffffffffu, cs, 4));
            cs = hadd2_(cs, __shfl_xor_sync(0xffffffffu, cs, 8));
            cs = hadd2_(cs, __shfl_xor_sync(0xffffffffu, cs, 16));
            if (lane < 4){
                float2 f = __half22float2(*(__half2*)&cs);
                int cb = colb*128 + wn*64 + ni*8 + 2*lane;
                atomicAdd(&g_colsum[cb],     f.x);
                atomicAdd(&g_colsum[cb + 1], f.y);
            }
        }
    }
}

// ---------------- loss assembly ----------------
// 2 threads per row (half=tid&1 handles 64 elems), grid 128 x 256
__global__ void loss_part()
{
    __shared__ float red[128];
    int tid = threadIdx.x;
    int row = blockIdx.x*128 + (tid >> 1);
    int half = tid & 1;
    const uint4* pi = (const uint4*)(g_ip + (size_t)row*PD + half*64);
    const uint4* pn = (const uint4*)(g_np + (size_t)row*PD + half*64);
    float dot = 0.f;
    #pragma unroll
    for (int i=0; i<8; i++){
        uint4 a = pi[i], b = pn[i];
        const __nv_bfloat162* pa = (const __nv_bfloat162*)&a;
        const __nv_bfloat162* pb = (const __nv_bfloat162*)&b;
        #pragma unroll
        for (int j=0; j<4; j++){
            float2 fa = __bfloat1622float2(pa[j]);
            float2 fb = __bfloat1622float2(pb[j]);
            dot += fa.x*fb.x + fa.y*fb.y;
        }
    }
    dot += __shfl_xor_sync(0xffffffffu, dot, 1);
    if (half == 0){
        red[tid >> 1] = 0.5f*(logf(g_rowsum[row]) + logf(g_colsum[row]))
                      - dot * 0.69314718055994531f;
    }
    __syncthreads();
    #pragma unroll
    for (int o=64; o; o>>=1){
        if (tid < o) red[tid] += red[tid + o];
        __syncthreads();
    }
    if (tid == 0) g_part[blockIdx.x] = red[0];
}

__global__ void loss_final(float* out)
{
    int l = threadIdx.x;
    float v = g_part[l] + g_part[l+32] + g_part[l+64] + g_part[l+96];
    #pragma unroll
    for (int o=16; o; o>>=1) v += __shfl_xor_sync(0xffffffffu, v, o);
    if (l == 0) out[0] = v * (1.0f/16384.0f);
}

// ---------------- launcher ----------------
extern "C" void kernel_launch(void* const* d_in, const int* in_sizes, int n_in,
                              void* d_out, int out_size)
{
    (void)in_sizes; (void)n_in; (void)out_size;
    const float* img = (const float*)d_in[0];
    const float* num = (const float*)d_in[1];
    const float* Wi1 = (const float*)d_in[2];
    const float* bi1 = (const float*)d_in[3];
    const float* Wi2 = (const float*)d_in[4];
    const float* bi2 = (const float*)d_in[5];
    const float* Wn1 = (const float*)d_in[6];
    const float* bn1 = (const float*)d_in[7];
    const float* Wn2 = (const float*)d_in[8];
    const float* bn2 = (const float*)d_in[9];
    const float* lt  = (const float*)d_in[10];
    float* out = (float*)d_out;

    int nsm = 148;
    cudaDeviceGetAttribute(&nsm, cudaDevAttrMultiProcessorCount, 0);

    cudaFuncSetAttribute(mlp_all,    cudaFuncAttributeMaxDynamicSharedMemorySize, MLP_SMEM);
    cudaFuncSetAttribute(logits_fp8, cudaFuncAttributeMaxDynamicSharedMemorySize, LOG_SMEM);

    convert_all<<<1024, 256>>>(Wi1, Wi2, Wn1, Wn2);                      // 1
    mlp_all<<<256, 256, MLP_SMEM>>>(img, num, bi1, bi2, bn1, bn2, lt);   // 2
    logits_fp8<<<3*nsm, 256, LOG_SMEM>>>();                              // 3
    loss_part<<<128, 256>>>();                                           // 4
    loss_final<<<1, 32>>>(out);                                          // 5
}